// round 9
// baseline (speedup 1.0000x reference)
#include <cuda_runtime.h>
#include <cuda_fp16.h>
#include <cstdint>

#define NN   100000
#define NE   1000000
#define NR   8
#define NH   4
#define FIN  64
#define FOUT 64
#define DH   16
#define NBLK 98              // ceil(NN / 1024)

// ---------------- scratch (device globals; allocation-free) ----------------
__device__ __align__(16) __half g_feat[(size_t)NR * NN * FOUT];  // 102.4 MB
__device__ __align__(16) float  g_el[(size_t)NR * NN * NH];      // 12.8 MB
__device__ __align__(16) float  g_er[(size_t)NR * NN * NH];      // 12.8 MB
__device__ int g_cnt[NN];
__device__ int g_off[NN + 1];
__device__ int g_wcur[NN];
__device__ int g_bsum[NBLK];
__device__ int g_btop[NBLK];
__device__ int g_epk[NE];                                        // 4 MB

typedef unsigned long long ull;

__device__ __forceinline__ ull pack_dup(float x) {
    ull r;
    asm("mov.b64 %0, {%1, %1};" : "=l"(r) : "f"(x));
    return r;
}
__device__ __forceinline__ ull fma2(ull a, ull b, ull c) {
    ull r;
    asm("fma.rn.f32x2 %0, %1, %2, %3;" : "=l"(r) : "l"(a), "l"(b), "l"(c));
    return r;
}
__device__ __forceinline__ void unpack2(ull v, float& lo, float& hi) {
    asm("mov.b64 {%0, %1}, %2;" : "=f"(lo), "=f"(hi) : "l"(v));
}
__device__ __forceinline__ unsigned h2_to_u32(__half2 h) {
    union { __half2 h; unsigned u; } c; c.h = h; return c.u;
}
__device__ __forceinline__ __half2 u32_to_h2(unsigned u) {
    union { unsigned u; __half2 h; } c; c.u = u; return c.h;
}

// ================= CSR build =================
__global__ void k_zero() {
    int i = blockIdx.x * blockDim.x + threadIdx.x;
    if (i < NN) g_cnt[i] = 0;
}
__global__ void k_hist(const int* __restrict__ dst) {
    int e = blockIdx.x * blockDim.x + threadIdx.x;
    if (e < NE) atomicAdd(&g_cnt[dst[e]], 1);
}
// per-block exclusive scan over 1024 items (256 threads x 4)
__global__ void __launch_bounds__(256) k_scan_block() {
    __shared__ int ssum[256];
    int b = blockIdx.x, t = threadIdx.x;
    int base = b * 1024 + t * 4;
    int v[4], s = 0;
#pragma unroll
    for (int q = 0; q < 4; q++) {
        int idx = base + q;
        v[q] = (idx < NN) ? g_cnt[idx] : 0;
        s += v[q];
    }
    ssum[t] = s;
    __syncthreads();
    // inclusive Hillis-Steele
#pragma unroll
    for (int off = 1; off < 256; off <<= 1) {
        int add = (t >= off) ? ssum[t - off] : 0;
        __syncthreads();
        ssum[t] += add;
        __syncthreads();
    }
    int excl = ssum[t] - s;
#pragma unroll
    for (int q = 0; q < 4; q++) {
        int idx = base + q;
        if (idx < NN) g_off[idx] = excl;
        excl += v[q];
    }
    if (t == 255) g_bsum[b] = ssum[255];
}
__global__ void k_scan_tops() {
    if (threadIdx.x == 0) {
        int run = 0;
        for (int b = 0; b < NBLK; b++) { g_btop[b] = run; run += g_bsum[b]; }
        g_off[NN] = run;   // == NE
    }
}
__global__ void __launch_bounds__(256) k_addoff() {
    int b = blockIdx.x, t = threadIdx.x;
    int add = g_btop[b];
    int base = b * 1024 + t * 4;
#pragma unroll
    for (int q = 0; q < 4; q++) {
        int idx = base + q;
        if (idx < NN) {
            int o = g_off[idx] + add;
            g_off[idx]  = o;
            g_wcur[idx] = o;
        }
    }
}
__global__ void k_scatter(const int* __restrict__ src, const int* __restrict__ dst,
                          const int* __restrict__ erel) {
    int e = blockIdx.x * blockDim.x + threadIdx.x;
    if (e >= NE) return;
    int d = dst[e];
    int pos = atomicAdd(&g_wcur[d], 1);
    g_epk[pos] = src[e] | (erel[e] << 20);
}

// ================= K1: feat = x @ W[r]  (+ fused el/er epilogue) ============
__global__ void __launch_bounds__(128) k_feat(const float* __restrict__ x,
                                              const float* __restrict__ W,
                                              const float* __restrict__ al,
                                              const float* __restrict__ ar) {
    __shared__ float xs[64][128];   // 32 KB
    __shared__ float ws[64][64];    // 16 KB
    const int r   = blockIdx.y;
    const int n0  = blockIdx.x * 128;
    const int tid = threadIdx.x;

    for (int k = tid; k < 64 * 64; k += 128) {
        int i = k >> 6, f = k & 63;
        ws[i][f] = W[(((size_t)(r * NH + (f >> 4)) * FIN + i) * DH) + (f & 15)];
    }
    {
        int gn = n0 + tid;
        const float4* x4 = (const float4*)x;
#pragma unroll
        for (int i4 = 0; i4 < 16; i4++) {
            float4 v = (gn < NN) ? x4[(size_t)gn * 16 + i4] : make_float4(0.f, 0.f, 0.f, 0.f);
            xs[i4 * 4 + 0][tid] = v.x;
            xs[i4 * 4 + 1][tid] = v.y;
            xs[i4 * 4 + 2][tid] = v.z;
            xs[i4 * 4 + 3][tid] = v.w;
        }
    }
    __syncthreads();

    const int fx = tid & 7;
    const int ny = tid >> 3;
    ull acc2[8][4];
#pragma unroll
    for (int a = 0; a < 8; a++)
#pragma unroll
        for (int p = 0; p < 4; p++) acc2[a][p] = 0ull;

#pragma unroll 4
    for (int i = 0; i < 64; i++) {
        float4 xa = *(const float4*)&xs[i][ny * 8];
        float4 xb = *(const float4*)&xs[i][ny * 8 + 4];
        ulonglong2 wlo = *(const ulonglong2*)&ws[i][fx * 8];
        ulonglong2 whi = *(const ulonglong2*)&ws[i][fx * 8 + 4];
        ull w2[4] = {wlo.x, wlo.y, whi.x, whi.y};
        float xv[8] = {xa.x, xa.y, xa.z, xa.w, xb.x, xb.y, xb.z, xb.w};
#pragma unroll
        for (int a = 0; a < 8; a++) {
            ull d = pack_dup(xv[a]);
#pragma unroll
            for (int p = 0; p < 4; p++) acc2[a][p] = fma2(d, w2[p], acc2[a][p]);
        }
    }

    float acc[8][8];
#pragma unroll
    for (int a = 0; a < 8; a++)
#pragma unroll
        for (int p = 0; p < 4; p++) unpack2(acc2[a][p], acc[a][2 * p], acc[a][2 * p + 1]);

    // store feat (fp16)
#pragma unroll
    for (int a = 0; a < 8; a++) {
        int n = n0 + ny * 8 + a;
        if (n < NN) {
            uint4 pk = make_uint4(h2_to_u32(__floats2half2_rn(acc[a][0], acc[a][1])),
                                  h2_to_u32(__floats2half2_rn(acc[a][2], acc[a][3])),
                                  h2_to_u32(__floats2half2_rn(acc[a][4], acc[a][5])),
                                  h2_to_u32(__floats2half2_rn(acc[a][6], acc[a][7])));
            *(uint4*)(g_feat + ((size_t)r * NN + n) * 64 + fx * 8) = pk;
        }
    }

    // fused el/er epilogue (fp32)
    {
        const int h  = fx >> 1;
        const int d0 = (fx & 1) * 8;
        const float* alp = al + (r * NH + h) * DH + d0;
        const float* arp = ar + (r * NH + h) * DH + d0;
        float alv[8], arv[8];
#pragma unroll
        for (int b = 0; b < 8; b++) { alv[b] = alp[b]; arv[b] = arp[b]; }
#pragma unroll
        for (int a = 0; a < 8; a++) {
            float pl = 0.f, pr = 0.f;
#pragma unroll
            for (int b = 0; b < 8; b++) { pl += acc[a][b] * alv[b]; pr += acc[a][b] * arv[b]; }
            pl += __shfl_xor_sync(0xFFFFFFFFu, pl, 1);
            pr += __shfl_xor_sync(0xFFFFFFFFu, pr, 1);
            int n = n0 + ny * 8 + a;
            if (n < NN) {
                if ((fx & 1) == 0)
                    g_el[((size_t)r * NN + n) * NH + h] = pl;
                else
                    g_er[((size_t)r * NN + n) * NH + h] = pr;
            }
        }
    }
}

// ================= K2: pull-mode aggregation, one warp per dst node =========
// lane l owns output cols (2l, 2l+1); head h = l >> 3
__global__ void __launch_bounds__(256) k_agg2(float* __restrict__ out,
                                              const float* __restrict__ bias) {
    int wid_in_blk = threadIdx.x >> 5;
    int lane = threadIdx.x & 31;
    int d = blockIdx.x * 8 + wid_in_blk;
    if (d >= NN) return;
    const int h = lane >> 3;

    int beg = g_off[d];
    int end = g_off[d + 1];

    float accx = 0.f, accy = 0.f, dn = 0.f;
    const size_t er_base = ((size_t)NN) * 0 + (size_t)d;   // er[(r*NN + d)*4 + h]

    for (int i = beg; i < end; i++) {
        int pk = g_epk[i];                      // broadcast load
        int s = pk & 0xFFFFF;
        int r = pk >> 20;
        // lanes 0-3: el[h'], lanes 4-7: er[h']
        float a = 0.f;
        if (lane < 4)
            a = g_el[(((size_t)r * NN + s) << 2) + lane];
        else if (lane < 8)
            a = g_er[(((size_t)r * NN + d) << 2) + (lane - 4)];
        float elh = __shfl_sync(0xFFFFFFFFu, a, h);
        float erh = __shfl_sync(0xFFFFFFFFu, a, 4 + h);
        float sv = elh + erh;
        float lv = sv > 0.f ? sv : 0.2f * sv;
        float ev = __expf(lv);
        dn += ev;
        unsigned f2 = *(const unsigned*)(g_feat + ((size_t)r * NN + s) * 64 + 2 * lane);
        float2 pf = __half22float2(u32_to_h2(f2));
        accx += pf.x * ev;
        accy += pf.y * ev;
    }

    float w;
    asm("rcp.approx.f32 %0, %1;" : "=f"(w) : "f"(fmaxf(dn, 1e-16f)));
    float2 o;
    o.x = accx * w + bias[2 * lane];
    o.y = accy * w + bias[2 * lane + 1];
    *(float2*)(out + (size_t)d * 64 + 2 * lane) = o;
}

// ---------------- launch ----------------
extern "C" void kernel_launch(void* const* d_in, const int* in_sizes, int n_in,
                              void* d_out, int out_size) {
    const float* x    = (const float*)d_in[0];
    const int*   srci = (const int*)d_in[1];
    const int*   dsti = (const int*)d_in[2];
    const int*   erel = (const int*)d_in[3];
    const float* W    = (const float*)d_in[4];
    const float* al   = (const float*)d_in[5];
    const float* ar   = (const float*)d_in[6];
    const float* bias = (const float*)d_in[7];
    float* out = (float*)d_out;
    (void)in_sizes; (void)n_in; (void)out_size;

    k_zero<<<(NN + 255) / 256, 256>>>();
    k_hist<<<(NE + 255) / 256, 256>>>(dsti);
    k_scan_block<<<NBLK, 256>>>();
    k_scan_tops<<<1, 32>>>();
    k_addoff<<<NBLK, 256>>>();
    k_scatter<<<(NE + 255) / 256, 256>>>(srci, dsti, erel);
    {
        dim3 grid((NN + 127) / 128, NR);
        k_feat<<<grid, 128>>>(x, W, al, ar);
    }
    k_agg2<<<(NN + 7) / 8, 256>>>(out, bias);
}

// round 10
// speedup vs baseline: 1.1984x; 1.1984x over previous
#include <cuda_runtime.h>
#include <cuda_fp16.h>
#include <cstdint>

#define NN   100000
#define NE   1000000
#define NR   8
#define NH   4
#define FIN  64
#define FOUT 64
#define DH   16
#define NBLK 98              // ceil(NN / 1024)

// ---------------- scratch (device globals; allocation-free) ----------------
__device__ __align__(16) __half g_feat[(size_t)NR * NN * FOUT];  // 102.4 MB
__device__ __align__(16) float  g_el[(size_t)NR * NN * NH];      // 12.8 MB
__device__ __align__(16) float  g_er[(size_t)NR * NN * NH];      // 12.8 MB
__device__ int   g_cnt[NN];
__device__ int   g_off[NN + 1];
__device__ int   g_wcur[NN];
__device__ int   g_bsum[NBLK];
__device__ int   g_btop[NBLK];
__device__ int   g_epk[NE];                                      // 4 MB  (idx = r*NN+s)
__device__ __align__(16) float g_ecsr[(size_t)NE * NH];          // 16 MB (ev per head, CSR order)

typedef unsigned long long ull;

__device__ __forceinline__ ull pack_dup(float x) {
    ull r;
    asm("mov.b64 %0, {%1, %1};" : "=l"(r) : "f"(x));
    return r;
}
__device__ __forceinline__ ull fma2(ull a, ull b, ull c) {
    ull r;
    asm("fma.rn.f32x2 %0, %1, %2, %3;" : "=l"(r) : "l"(a), "l"(b), "l"(c));
    return r;
}
__device__ __forceinline__ void unpack2(ull v, float& lo, float& hi) {
    asm("mov.b64 {%0, %1}, %2;" : "=f"(lo), "=f"(hi) : "l"(v));
}
__device__ __forceinline__ unsigned h2_to_u32(__half2 h) {
    union { __half2 h; unsigned u; } c; c.h = h; return c.u;
}
__device__ __forceinline__ __half2 u32_to_h2(unsigned u) {
    union { unsigned u; __half2 h; } c; c.u = u; return c.h;
}

// ================= CSR build =================
__global__ void k_zero() {
    int i = blockIdx.x * blockDim.x + threadIdx.x;
    if (i < NN) g_cnt[i] = 0;
}
__global__ void k_hist(const int* __restrict__ dst) {
    int e = blockIdx.x * blockDim.x + threadIdx.x;
    if (e < NE) atomicAdd(&g_cnt[dst[e]], 1);
}
__global__ void __launch_bounds__(256) k_scan_block() {
    __shared__ int ssum[256];
    int b = blockIdx.x, t = threadIdx.x;
    int base = b * 1024 + t * 4;
    int v[4], s = 0;
#pragma unroll
    for (int q = 0; q < 4; q++) {
        int idx = base + q;
        v[q] = (idx < NN) ? g_cnt[idx] : 0;
        s += v[q];
    }
    ssum[t] = s;
    __syncthreads();
#pragma unroll
    for (int off = 1; off < 256; off <<= 1) {
        int add = (t >= off) ? ssum[t - off] : 0;
        __syncthreads();
        ssum[t] += add;
        __syncthreads();
    }
    int excl = ssum[t] - s;
#pragma unroll
    for (int q = 0; q < 4; q++) {
        int idx = base + q;
        if (idx < NN) g_off[idx] = excl;
        excl += v[q];
    }
    if (t == 255) g_bsum[b] = ssum[255];
}
// parallel scan over NBLK block sums (NBLK <= 128)
__global__ void __launch_bounds__(128) k_scan_tops() {
    __shared__ int sv[128];
    int t = threadIdx.x;
    int v = (t < NBLK) ? g_bsum[t] : 0;
    sv[t] = v;
    __syncthreads();
#pragma unroll
    for (int off = 1; off < 128; off <<= 1) {
        int add = (t >= off) ? sv[t - off] : 0;
        __syncthreads();
        sv[t] += add;
        __syncthreads();
    }
    if (t < NBLK) g_btop[t] = sv[t] - v;   // exclusive
    if (t == NBLK - 1) g_off[NN] = sv[t];
}
__global__ void __launch_bounds__(256) k_addoff() {
    int b = blockIdx.x, t = threadIdx.x;
    int add = g_btop[b];
    int base = b * 1024 + t * 4;
#pragma unroll
    for (int q = 0; q < 4; q++) {
        int idx = base + q;
        if (idx < NN) {
            int o = g_off[idx] + add;
            g_off[idx]  = o;
            g_wcur[idx] = o;
        }
    }
}
// scatter + fused exp: writes idx and per-head ev in CSR order
__global__ void k_scatter(const int* __restrict__ src, const int* __restrict__ dst,
                          const int* __restrict__ erel) {
    int e = blockIdx.x * blockDim.x + threadIdx.x;
    if (e >= NE) return;
    int d = dst[e], s = src[e], r = erel[e];
    int idx = r * NN + s;
    float4 el = ((const float4*)g_el)[idx];
    float4 er = ((const float4*)g_er)[(size_t)r * NN + d];
    float sv[4] = {el.x + er.x, el.y + er.y, el.z + er.z, el.w + er.w};
    float ev[4];
#pragma unroll
    for (int h = 0; h < 4; h++) {
        float lv = sv[h] > 0.f ? sv[h] : 0.2f * sv[h];
        ev[h] = __expf(lv);
    }
    int pos = atomicAdd(&g_wcur[d], 1);
    g_epk[pos] = idx;
    ((float4*)g_ecsr)[pos] = make_float4(ev[0], ev[1], ev[2], ev[3]);
}

// ================= K1: feat = x @ W[r]  (+ fused el/er epilogue) ============
__global__ void __launch_bounds__(128) k_feat(const float* __restrict__ x,
                                              const float* __restrict__ W,
                                              const float* __restrict__ al,
                                              const float* __restrict__ ar) {
    __shared__ float xs[64][128];   // 32 KB
    __shared__ float ws[64][64];    // 16 KB
    const int r   = blockIdx.y;
    const int n0  = blockIdx.x * 128;
    const int tid = threadIdx.x;

    for (int k = tid; k < 64 * 64; k += 128) {
        int i = k >> 6, f = k & 63;
        ws[i][f] = W[(((size_t)(r * NH + (f >> 4)) * FIN + i) * DH) + (f & 15)];
    }
    {
        int gn = n0 + tid;
        const float4* x4 = (const float4*)x;
#pragma unroll
        for (int i4 = 0; i4 < 16; i4++) {
            float4 v = (gn < NN) ? x4[(size_t)gn * 16 + i4] : make_float4(0.f, 0.f, 0.f, 0.f);
            xs[i4 * 4 + 0][tid] = v.x;
            xs[i4 * 4 + 1][tid] = v.y;
            xs[i4 * 4 + 2][tid] = v.z;
            xs[i4 * 4 + 3][tid] = v.w;
        }
    }
    __syncthreads();

    const int fx = tid & 7;
    const int ny = tid >> 3;
    ull acc2[8][4];
#pragma unroll
    for (int a = 0; a < 8; a++)
#pragma unroll
        for (int p = 0; p < 4; p++) acc2[a][p] = 0ull;

#pragma unroll 4
    for (int i = 0; i < 64; i++) {
        float4 xa = *(const float4*)&xs[i][ny * 8];
        float4 xb = *(const float4*)&xs[i][ny * 8 + 4];
        ulonglong2 wlo = *(const ulonglong2*)&ws[i][fx * 8];
        ulonglong2 whi = *(const ulonglong2*)&ws[i][fx * 8 + 4];
        ull w2[4] = {wlo.x, wlo.y, whi.x, whi.y};
        float xv[8] = {xa.x, xa.y, xa.z, xa.w, xb.x, xb.y, xb.z, xb.w};
#pragma unroll
        for (int a = 0; a < 8; a++) {
            ull d = pack_dup(xv[a]);
#pragma unroll
            for (int p = 0; p < 4; p++) acc2[a][p] = fma2(d, w2[p], acc2[a][p]);
        }
    }

    float acc[8][8];
#pragma unroll
    for (int a = 0; a < 8; a++)
#pragma unroll
        for (int p = 0; p < 4; p++) unpack2(acc2[a][p], acc[a][2 * p], acc[a][2 * p + 1]);

    // store feat (fp16)
#pragma unroll
    for (int a = 0; a < 8; a++) {
        int n = n0 + ny * 8 + a;
        if (n < NN) {
            uint4 pk = make_uint4(h2_to_u32(__floats2half2_rn(acc[a][0], acc[a][1])),
                                  h2_to_u32(__floats2half2_rn(acc[a][2], acc[a][3])),
                                  h2_to_u32(__floats2half2_rn(acc[a][4], acc[a][5])),
                                  h2_to_u32(__floats2half2_rn(acc[a][6], acc[a][7])));
            *(uint4*)(g_feat + ((size_t)r * NN + n) * 64 + fx * 8) = pk;
        }
    }

    // fused el/er epilogue (fp32)
    {
        const int h  = fx >> 1;
        const int d0 = (fx & 1) * 8;
        const float* alp = al + (r * NH + h) * DH + d0;
        const float* arp = ar + (r * NH + h) * DH + d0;
        float alv[8], arv[8];
#pragma unroll
        for (int b = 0; b < 8; b++) { alv[b] = alp[b]; arv[b] = arp[b]; }
#pragma unroll
        for (int a = 0; a < 8; a++) {
            float pl = 0.f, pr = 0.f;
#pragma unroll
            for (int b = 0; b < 8; b++) { pl += acc[a][b] * alv[b]; pr += acc[a][b] * arv[b]; }
            pl += __shfl_xor_sync(0xFFFFFFFFu, pl, 1);
            pr += __shfl_xor_sync(0xFFFFFFFFu, pr, 1);
            int n = n0 + ny * 8 + a;
            if (n < NN) {
                if ((fx & 1) == 0)
                    g_el[((size_t)r * NN + n) * NH + h] = pl;
                else
                    g_er[((size_t)r * NN + n) * NH + h] = pr;
            }
        }
    }
}

// ================= K2: pull-mode aggregation, one warp per dst node =========
// lane l owns output cols (2l, 2l+1); head h = l >> 3; ev precomputed in CSR order
__global__ void __launch_bounds__(256) k_agg2(float* __restrict__ out,
                                              const float* __restrict__ bias) {
    int wid_in_blk = threadIdx.x >> 5;
    int lane = threadIdx.x & 31;
    int d = blockIdx.x * 8 + wid_in_blk;
    if (d >= NN) return;
    const int h = lane >> 3;

    int beg = g_off[d];
    int end = g_off[d + 1];

    float accx = 0.f, accy = 0.f, dn = 0.f;

    int i = beg;
    for (; i + 2 <= end; i += 2) {
        // issue all loads for both edges up front
        int idx0 = g_epk[i];
        int idx1 = g_epk[i + 1];
        float ev0 = g_ecsr[(size_t)(i) * 4 + h];
        float ev1 = g_ecsr[(size_t)(i + 1) * 4 + h];
        unsigned f0 = *(const unsigned*)(g_feat + (size_t)idx0 * 64 + 2 * lane);
        unsigned f1 = *(const unsigned*)(g_feat + (size_t)idx1 * 64 + 2 * lane);
        float2 p0 = __half22float2(u32_to_h2(f0));
        float2 p1 = __half22float2(u32_to_h2(f1));
        dn += ev0 + ev1;
        accx += p0.x * ev0 + p1.x * ev1;
        accy += p0.y * ev0 + p1.y * ev1;
    }
    if (i < end) {
        int idx0 = g_epk[i];
        float ev0 = g_ecsr[(size_t)i * 4 + h];
        unsigned f0 = *(const unsigned*)(g_feat + (size_t)idx0 * 64 + 2 * lane);
        float2 p0 = __half22float2(u32_to_h2(f0));
        dn += ev0;
        accx += p0.x * ev0;
        accy += p0.y * ev0;
    }

    float w;
    asm("rcp.approx.f32 %0, %1;" : "=f"(w) : "f"(fmaxf(dn, 1e-16f)));
    float2 o;
    o.x = accx * w + bias[2 * lane];
    o.y = accy * w + bias[2 * lane + 1];
    *(float2*)(out + (size_t)d * 64 + 2 * lane) = o;
}

// ---------------- launch ----------------
extern "C" void kernel_launch(void* const* d_in, const int* in_sizes, int n_in,
                              void* d_out, int out_size) {
    const float* x    = (const float*)d_in[0];
    const int*   srci = (const int*)d_in[1];
    const int*   dsti = (const int*)d_in[2];
    const int*   erel = (const int*)d_in[3];
    const float* W    = (const float*)d_in[4];
    const float* al   = (const float*)d_in[5];
    const float* ar   = (const float*)d_in[6];
    const float* bias = (const float*)d_in[7];
    float* out = (float*)d_out;
    (void)in_sizes; (void)n_in; (void)out_size;

    k_zero<<<(NN + 255) / 256, 256>>>();
    k_hist<<<(NE + 255) / 256, 256>>>(dsti);
    k_scan_block<<<NBLK, 256>>>();
    k_scan_tops<<<1, 128>>>();
    k_addoff<<<NBLK, 256>>>();
    {
        dim3 grid((NN + 127) / 128, NR);
        k_feat<<<grid, 128>>>(x, W, al, ar);
    }
    k_scatter<<<(NE + 255) / 256, 256>>>(srci, dsti, erel);
    k_agg2<<<(NN + 7) / 8, 256>>>(out, bias);
}